// round 6
// baseline (speedup 1.0000x reference)
#include <cuda_runtime.h>
#include <cuda_bf16.h>

// inputs [B=2,T=16,V=10000,F=32] f32; L_vals[160000] f32; L_rows sorted i32; L_cols i32
// out[bt,i,f] = sum_{e: rows[e]==i} vals[e] * x[bt,cols[e],f]

#define BT    32
#define NV    10000
#define NF    32
#define NNZ_  160000

#define WARPS_CTA 4             // small CTA: finer retirement granularity
#define BT_PER    4             // bt slices covered by one warp (float4 lanes)
#define BTG       (BT / BT_PER) // 8 bt-groups

__device__ int g_row_ptr[NV + 1];

// row_ptr[v] = lower_bound(rows, v); rows sorted ascending.
__global__ void build_row_ptr_kernel(const int* __restrict__ rows) {
    int v = blockIdx.x * blockDim.x + threadIdx.x;
    if (v > NV) return;
    int lo = 0, hi = NNZ_;
    while (lo < hi) {
        int mid = (lo + hi) >> 1;
        if (__ldg(rows + mid) < v) lo = mid + 1;
        else                       hi = mid;
    }
    g_row_ptr[v] = lo;
}

#define GATHER_FMA(ACC, W, G)                 \
    do {                                      \
        (ACC).x = fmaf((W), (G).x, (ACC).x);  \
        (ACC).y = fmaf((W), (G).y, (ACC).y);  \
        (ACC).z = fmaf((W), (G).z, (ACC).z);  \
        (ACC).w = fmaf((W), (G).w, (ACC).w);  \
    } while (0)

// One warp per (vertex v, bt-group). Lane = slice_in_group*8 + f4chunk: one
// LDG.128 per edge fetches the 128B feature row across 4 bt slices at once.
// cols/vals loaded coalesced (32 edges / 2 loads), distributed by shfl.
// 8 gathers in flight per warp, dual accumulators.
__global__ void __launch_bounds__(WARPS_CTA * 32) spmm_v4_kernel(
    const float* __restrict__ x,      // [BT, V, F]
    const float* __restrict__ vals,   // [NNZ]
    const int*   __restrict__ cols,   // [NNZ]
    float*       __restrict__ out)    // [BT, V, F]
{
    const int warp = threadIdx.x >> 5;
    const int lane = threadIdx.x & 31;
    const int v    = blockIdx.x * WARPS_CTA + warp;
    if (v >= NV) return;   // uniform per warp

    const int btg = blockIdx.y;               // 0..7
    const int bt  = btg * BT_PER + (lane >> 3);
    const int f4  = lane & 7;

    const float4* __restrict__ xs =
        (const float4*)(x + (size_t)bt * NV * NF) + f4;

    const int s = g_row_ptr[v];
    const int e = g_row_ptr[v + 1];

    float4 acc0 = make_float4(0.f, 0.f, 0.f, 0.f);
    float4 acc1 = make_float4(0.f, 0.f, 0.f, 0.f);

    for (int base = s; base < e; base += 32) {
        int n = e - base;                     // uniform across warp
        if (n > 32) n = 32;
        int idx = min(base + lane, NNZ_ - 1); // clamp; excess lanes never consumed
        int   c = __ldg(cols + idx);
        float w = __ldg(vals + idx);

        int j = 0;
        #pragma unroll 1
        for (; j + 7 < n; j += 8) {
            int c0 = __shfl_sync(0xffffffffu, c, j);
            int c1 = __shfl_sync(0xffffffffu, c, j + 1);
            int c2 = __shfl_sync(0xffffffffu, c, j + 2);
            int c3 = __shfl_sync(0xffffffffu, c, j + 3);
            int c4 = __shfl_sync(0xffffffffu, c, j + 4);
            int c5 = __shfl_sync(0xffffffffu, c, j + 5);
            int c6 = __shfl_sync(0xffffffffu, c, j + 6);
            int c7 = __shfl_sync(0xffffffffu, c, j + 7);
            float w0 = __shfl_sync(0xffffffffu, w, j);
            float w1 = __shfl_sync(0xffffffffu, w, j + 1);
            float w2 = __shfl_sync(0xffffffffu, w, j + 2);
            float w3 = __shfl_sync(0xffffffffu, w, j + 3);
            float w4 = __shfl_sync(0xffffffffu, w, j + 4);
            float w5 = __shfl_sync(0xffffffffu, w, j + 5);
            float w6 = __shfl_sync(0xffffffffu, w, j + 6);
            float w7 = __shfl_sync(0xffffffffu, w, j + 7);
            float4 g0 = __ldg(xs + (size_t)c0 * 8);
            float4 g1 = __ldg(xs + (size_t)c1 * 8);
            float4 g2 = __ldg(xs + (size_t)c2 * 8);
            float4 g3 = __ldg(xs + (size_t)c3 * 8);
            float4 g4 = __ldg(xs + (size_t)c4 * 8);
            float4 g5 = __ldg(xs + (size_t)c5 * 8);
            float4 g6 = __ldg(xs + (size_t)c6 * 8);
            float4 g7 = __ldg(xs + (size_t)c7 * 8);
            GATHER_FMA(acc0, w0, g0);
            GATHER_FMA(acc1, w1, g1);
            GATHER_FMA(acc0, w2, g2);
            GATHER_FMA(acc1, w3, g3);
            GATHER_FMA(acc0, w4, g4);
            GATHER_FMA(acc1, w5, g5);
            GATHER_FMA(acc0, w6, g6);
            GATHER_FMA(acc1, w7, g7);
        }
        #pragma unroll 1
        for (; j + 3 < n; j += 4) {
            int c0 = __shfl_sync(0xffffffffu, c, j);
            int c1 = __shfl_sync(0xffffffffu, c, j + 1);
            int c2 = __shfl_sync(0xffffffffu, c, j + 2);
            int c3 = __shfl_sync(0xffffffffu, c, j + 3);
            float w0 = __shfl_sync(0xffffffffu, w, j);
            float w1 = __shfl_sync(0xffffffffu, w, j + 1);
            float w2 = __shfl_sync(0xffffffffu, w, j + 2);
            float w3 = __shfl_sync(0xffffffffu, w, j + 3);
            float4 g0 = __ldg(xs + (size_t)c0 * 8);
            float4 g1 = __ldg(xs + (size_t)c1 * 8);
            float4 g2 = __ldg(xs + (size_t)c2 * 8);
            float4 g3 = __ldg(xs + (size_t)c3 * 8);
            GATHER_FMA(acc0, w0, g0);
            GATHER_FMA(acc1, w1, g1);
            GATHER_FMA(acc0, w2, g2);
            GATHER_FMA(acc1, w3, g3);
        }
        #pragma unroll 1
        for (; j < n; ++j) {
            int   c0 = __shfl_sync(0xffffffffu, c, j);
            float w0 = __shfl_sync(0xffffffffu, w, j);
            float4 g0 = __ldg(xs + (size_t)c0 * 8);
            GATHER_FMA(acc0, w0, g0);
        }
    }

    float4 r;
    r.x = acc0.x + acc1.x;
    r.y = acc0.y + acc1.y;
    r.z = acc0.z + acc1.z;
    r.w = acc0.w + acc1.w;

    float4* o = (float4*)(out + (size_t)bt * NV * NF + (size_t)v * NF) + f4;
    *o = r;
}

extern "C" void kernel_launch(void* const* d_in, const int* in_sizes, int n_in,
                              void* d_out, int out_size) {
    const float* x    = (const float*)d_in[0];
    const float* vals = (const float*)d_in[1];
    const int*   rows = (const int*)  d_in[2];
    const int*   cols = (const int*)  d_in[3];
    float*       out  = (float*)d_out;

    (void)in_sizes; (void)n_in; (void)out_size;

    build_row_ptr_kernel<<<(NV + 1 + 255) / 256, 256>>>(rows);

    dim3 grid((NV + WARPS_CTA - 1) / WARPS_CTA, BTG);
    spmm_v4_kernel<<<grid, WARPS_CTA * 32>>>(x, vals, cols, out);
}

// round 7
// speedup vs baseline: 1.1262x; 1.1262x over previous
#include <cuda_runtime.h>
#include <cuda_fp16.h>

// inputs [B=2,T=16,V=10000,F=32] f32; L_vals[160000] f32; L_rows sorted i32; L_cols i32
// out[bt,i,f] = sum_{e: rows[e]==i} vals[e] * x[bt,cols[e],f]
//
// Strategy: convert x to fp16 in a PAIRED layout so one 128B line holds the
// 32-feature rows of TWO bt slices for a vertex:
//   g_xh[pair p][vertex v] = 128B line = [slice 2p (32 half)] [slice 2p+1 (32 half)]
// Gather: one LDG.128 per edge covers 8 slices (4 lines) -> L1 wavefronts and
// L2 fill bytes both halve vs f32. Accumulate fp32.

#define BT    32
#define NV    10000
#define NF    32
#define NNZ_  160000
#define NPAIR 16          // bt slice pairs
#define PG    4           // pair-groups: 4 pairs = 8 slices per warp

#define WARPS_CTA 4

__device__ int g_row_ptr[NV + 1];
// fp16 paired x: [NPAIR][NV][64 halves] = 20.48 MB, 16B aligned via uint4.
__device__ uint4 g_xh4[(size_t)NPAIR * NV * 8];

// row_ptr[v] = lower_bound(rows, v); rows sorted ascending.
__global__ void build_row_ptr_kernel(const int* __restrict__ rows) {
    int v = blockIdx.x * blockDim.x + threadIdx.x;
    if (v > NV) return;
    int lo = 0, hi = NNZ_;
    while (lo < hi) {
        int mid = (lo + hi) >> 1;
        if (__ldg(rows + mid) < v) lo = mid + 1;
        else                       hi = mid;
    }
    g_row_ptr[v] = lo;
}

// Convert f32 x -> paired fp16. blockIdx.y = pair p. Each thread converts 4 floats.
// tid -> (v, s, ch): v = tid>>4, s = (tid>>3)&1, ch = tid&7 (ch = float4 chunk of row).
__global__ void __launch_bounds__(256) convert_kernel(const float* __restrict__ x) {
    int p   = blockIdx.y;
    int tid = blockIdx.x * 256 + threadIdx.x;     // 160000 per pair
    int v   = tid >> 4;
    if (v >= NV) return;
    int s   = (tid >> 3) & 1;
    int ch  = tid & 7;

    const float4 f = *(const float4*)(x + ((size_t)(2 * p + s) * NV + v) * NF + ch * 4);
    __half2 h0 = __floats2half2_rn(f.x, f.y);
    __half2 h1 = __floats2half2_rn(f.z, f.w);

    char* base = (char*)g_xh4;
    // byte offset: line (p,v) is 128B; slice half is 64B; chunk is 8B.
    size_t off = ((size_t)p * NV + v) * 128 + (size_t)s * 64 + (size_t)ch * 8;
    uint2 pk = make_uint2(*(const unsigned*)&h0, *(const unsigned*)&h1);
    *(uint2*)(base + off) = pk;
}

__device__ __forceinline__ void fma8(float acc[8], uint4 g, float w) {
    __half2 h; float2 f;
    h = *(__half2*)&g.x; f = __half22float2(h);
    acc[0] = fmaf(w, f.x, acc[0]); acc[1] = fmaf(w, f.y, acc[1]);
    h = *(__half2*)&g.y; f = __half22float2(h);
    acc[2] = fmaf(w, f.x, acc[2]); acc[3] = fmaf(w, f.y, acc[3]);
    h = *(__half2*)&g.z; f = __half22float2(h);
    acc[4] = fmaf(w, f.x, acc[4]); acc[5] = fmaf(w, f.y, acc[5]);
    h = *(__half2*)&g.w; f = __half22float2(h);
    acc[6] = fmaf(w, f.x, acc[6]); acc[7] = fmaf(w, f.y, acc[7]);
}

// One warp per (vertex v, pair-group pg of 4 pairs = 8 slices).
// Lane = pp*8 + c: pp = pair-in-group (0..3), c = 16B chunk of the 128B line.
// Lane's 8 halves belong to slice bt = 2*(pg*4+pp) + (c>>2), features (c&3)*8.. .
// One LDG.128 per edge gathers 8 slices' rows (4 lines).
__global__ void __launch_bounds__(WARPS_CTA * 32) spmm_h_kernel(
    const float* __restrict__ vals,   // [NNZ]
    const int*   __restrict__ cols,   // [NNZ]
    float*       __restrict__ out)    // [BT, V, F]
{
    const int warp = threadIdx.x >> 5;
    const int lane = threadIdx.x & 31;
    const int v    = blockIdx.x * WARPS_CTA + warp;   // grid.x*4 == NV exactly
    const int pg   = blockIdx.y;

    const int pp = lane >> 3;
    const int c  = lane & 7;
    const int p  = pg * 4 + pp;
    const int bt = 2 * p + (c >> 2);
    const int f0 = (c & 3) * 8;

    // per-lane gather base: uint4 index = (p*NV + col)*8 + c
    const uint4* __restrict__ xp = g_xh4 + (size_t)p * NV * 8 + c;

    const int s = g_row_ptr[v];
    const int e = g_row_ptr[v + 1];

    float acc[8] = {0.f, 0.f, 0.f, 0.f, 0.f, 0.f, 0.f, 0.f};

    for (int base = s; base < e; base += 32) {
        int n = e - base;                      // uniform across warp
        if (n > 32) n = 32;
        int idx = min(base + lane, NNZ_ - 1);  // clamp; excess lanes never consumed
        int   cc = __ldg(cols + idx);
        float ww = __ldg(vals + idx);

        int j = 0;
        #pragma unroll 1
        for (; j + 3 < n; j += 4) {
            int   c0 = __shfl_sync(0xffffffffu, cc, j);
            int   c1 = __shfl_sync(0xffffffffu, cc, j + 1);
            int   c2 = __shfl_sync(0xffffffffu, cc, j + 2);
            int   c3 = __shfl_sync(0xffffffffu, cc, j + 3);
            float w0 = __shfl_sync(0xffffffffu, ww, j);
            float w1 = __shfl_sync(0xffffffffu, ww, j + 1);
            float w2 = __shfl_sync(0xffffffffu, ww, j + 2);
            float w3 = __shfl_sync(0xffffffffu, ww, j + 3);
            uint4 g0 = __ldg(xp + (size_t)c0 * 8);
            uint4 g1 = __ldg(xp + (size_t)c1 * 8);
            uint4 g2 = __ldg(xp + (size_t)c2 * 8);
            uint4 g3 = __ldg(xp + (size_t)c3 * 8);
            fma8(acc, g0, w0);
            fma8(acc, g1, w1);
            fma8(acc, g2, w2);
            fma8(acc, g3, w3);
        }
        #pragma unroll 1
        for (; j < n; ++j) {
            int   c0 = __shfl_sync(0xffffffffu, cc, j);
            float w0 = __shfl_sync(0xffffffffu, ww, j);
            uint4 g0 = __ldg(xp + (size_t)c0 * 8);
            fma8(acc, g0, w0);
        }
    }

    float* o = out + ((size_t)bt * NV + v) * NF + f0;
    *(float4*)(o)     = make_float4(acc[0], acc[1], acc[2], acc[3]);
    *(float4*)(o + 4) = make_float4(acc[4], acc[5], acc[6], acc[7]);
}

extern "C" void kernel_launch(void* const* d_in, const int* in_sizes, int n_in,
                              void* d_out, int out_size) {
    const float* x    = (const float*)d_in[0];
    const float* vals = (const float*)d_in[1];
    const int*   rows = (const int*)  d_in[2];
    const int*   cols = (const int*)  d_in[3];
    float*       out  = (float*)d_out;

    (void)in_sizes; (void)n_in; (void)out_size;

    build_row_ptr_kernel<<<(NV + 1 + 255) / 256, 256>>>(rows);

    // Convert x to paired fp16: 16 pairs x 160000 threads.
    dim3 cgrid((NV * 16 + 255) / 256, NPAIR);
    convert_kernel<<<cgrid, 256>>>(x);

    // SpMM: warp per (v, pair-group). grid = (NV/4, 4).
    dim3 grid(NV / WARPS_CTA, PG);
    spmm_h_kernel<<<grid, WARPS_CTA * 32>>>(vals, cols, out);
}

// round 8
// speedup vs baseline: 1.4006x; 1.2436x over previous
#include <cuda_runtime.h>
#include <cuda_fp16.h>

// inputs [B=2,T=16,V=10000,F=32] f32; L_vals[160000] f32; L_rows sorted i32; L_cols i32
// out[bt,i,f] = sum_{e: rows[e]==i} vals[e] * x[bt,cols[e],f]
//
// Pipeline:
//  1) prep_kernel (fused):
//     - blocks [0, CONV_BLOCKS): convert x to PAIRED fp16 layout, one 128B line
//       per (pair p, vertex v) = [slice 2p: 32 half][slice 2p+1: 32 half]
//     - blocks [CONV_BLOCKS, ...): boundary-scatter CSR row_ptr from sorted rows
//  2) spmm_h_kernel: warp per (vertex, 4-pair group); one LDG.128 per edge
//     gathers 8 slices (4 lines). fp32 accumulate.

#define BT    32
#define NV    10000
#define NF    32
#define NNZ_  160000
#define NPAIR 16
#define PG    4               // pair-groups of 4 pairs (8 slices) per warp

#define WARPS_CTA 4

#define CONV_THREADS (NPAIR * NV * 8)        // 1,280,000 (one 16B chunk each)
#define CONV_BLOCKS  (CONV_THREADS / 256)    // 5000
#define SCAT_BLOCKS  ((NNZ_ + 255) / 256)    // 625

__device__ int g_row_ptr[NV + 1];
// fp16 paired x: [NPAIR][NV] lines of 8 uint4 (128B) = 20.48 MB (L2-resident).
__device__ uint4 g_xh4[(size_t)NPAIR * NV * 8];

__global__ void __launch_bounds__(256) prep_kernel(
    const float* __restrict__ x, const int* __restrict__ rows)
{
    if (blockIdx.x < CONV_BLOCKS) {
        // ---- convert: thread -> (p, v, s, q); 32B read, 16B write ----
        int gtid = blockIdx.x * 256 + threadIdx.x;
        int p    = gtid / (NV * 8);
        int rem  = gtid - p * (NV * 8);
        int v    = rem >> 3;
        int s    = (rem >> 2) & 1;   // slice within pair
        int q    = rem & 3;          // 16B chunk within the 64B slice-half

        const float4* src =
            (const float4*)(x + ((size_t)(2 * p + s) * NV + v) * NF + q * 8);
        float4 a = __ldg(src);
        float4 b = __ldg(src + 1);

        __half2 h0 = __floats2half2_rn(a.x, a.y);
        __half2 h1 = __floats2half2_rn(a.z, a.w);
        __half2 h2 = __floats2half2_rn(b.x, b.y);
        __half2 h3 = __floats2half2_rn(b.z, b.w);
        uint4 pk;
        pk.x = *(const unsigned*)&h0;
        pk.y = *(const unsigned*)&h1;
        pk.z = *(const unsigned*)&h2;
        pk.w = *(const unsigned*)&h3;

        g_xh4[((size_t)p * NV + v) * 8 + s * 4 + q] = pk;
    } else {
        // ---- CSR row_ptr boundary scatter (rows sorted ascending) ----
        int e = (blockIdx.x - CONV_BLOCKS) * 256 + threadIdx.x;
        if (e >= NNZ_) return;
        int r  = __ldg(rows + e);
        int rp = (e == 0) ? -1 : __ldg(rows + e - 1);
        for (int v = rp + 1; v <= r; ++v) g_row_ptr[v] = e;
        if (e == NNZ_ - 1)
            for (int v = r + 1; v <= NV; ++v) g_row_ptr[v] = NNZ_;
    }
}

__device__ __forceinline__ void fma8(float acc[8], uint4 g, float w) {
    __half2 h; float2 f;
    h = *(__half2*)&g.x; f = __half22float2(h);
    acc[0] = fmaf(w, f.x, acc[0]); acc[1] = fmaf(w, f.y, acc[1]);
    h = *(__half2*)&g.y; f = __half22float2(h);
    acc[2] = fmaf(w, f.x, acc[2]); acc[3] = fmaf(w, f.y, acc[3]);
    h = *(__half2*)&g.z; f = __half22float2(h);
    acc[4] = fmaf(w, f.x, acc[4]); acc[5] = fmaf(w, f.y, acc[5]);
    h = *(__half2*)&g.w; f = __half22float2(h);
    acc[6] = fmaf(w, f.x, acc[6]); acc[7] = fmaf(w, f.y, acc[7]);
}

// One warp per (vertex v, pair-group pg of 4 pairs = 8 slices).
// Lane = pp*8 + c: pp = pair-in-group, c = 16B chunk of the 128B line.
// One LDG.128 per edge gathers 8 slices' feature rows (4 lines).
__global__ void __launch_bounds__(WARPS_CTA * 32) spmm_h_kernel(
    const float* __restrict__ vals,   // [NNZ]
    const int*   __restrict__ cols,   // [NNZ]
    float*       __restrict__ out)    // [BT, V, F]
{
    const int warp = threadIdx.x >> 5;
    const int lane = threadIdx.x & 31;
    const int v    = blockIdx.x * WARPS_CTA + warp;   // grid.x*4 == NV exactly
    const int pg   = blockIdx.y;

    const int pp = lane >> 3;
    const int c  = lane & 7;
    const int p  = pg * 4 + pp;
    const int bt = 2 * p + (c >> 2);
    const int f0 = (c & 3) * 8;

    const uint4* __restrict__ xp = g_xh4 + (size_t)p * NV * 8 + c;

    const int s = g_row_ptr[v];
    const int e = g_row_ptr[v + 1];

    float acc[8] = {0.f, 0.f, 0.f, 0.f, 0.f, 0.f, 0.f, 0.f};

    for (int base = s; base < e; base += 32) {
        int n = e - base;                      // uniform across warp
        if (n > 32) n = 32;
        int idx = min(base + lane, NNZ_ - 1);  // clamp; excess lanes never consumed
        int   cc = __ldg(cols + idx);
        float ww = __ldg(vals + idx);

        int j = 0;
        #pragma unroll 1
        for (; j + 3 < n; j += 4) {
            int   c0 = __shfl_sync(0xffffffffu, cc, j);
            int   c1 = __shfl_sync(0xffffffffu, cc, j + 1);
            int   c2 = __shfl_sync(0xffffffffu, cc, j + 2);
            int   c3 = __shfl_sync(0xffffffffu, cc, j + 3);
            float w0 = __shfl_sync(0xffffffffu, ww, j);
            float w1 = __shfl_sync(0xffffffffu, ww, j + 1);
            float w2 = __shfl_sync(0xffffffffu, ww, j + 2);
            float w3 = __shfl_sync(0xffffffffu, ww, j + 3);
            uint4 g0 = __ldg(xp + (size_t)c0 * 8);
            uint4 g1 = __ldg(xp + (size_t)c1 * 8);
            uint4 g2 = __ldg(xp + (size_t)c2 * 8);
            uint4 g3 = __ldg(xp + (size_t)c3 * 8);
            fma8(acc, g0, w0);
            fma8(acc, g1, w1);
            fma8(acc, g2, w2);
            fma8(acc, g3, w3);
        }
        #pragma unroll 1
        for (; j < n; ++j) {
            int   c0 = __shfl_sync(0xffffffffu, cc, j);
            float w0 = __shfl_sync(0xffffffffu, ww, j);
            uint4 g0 = __ldg(xp + (size_t)c0 * 8);
            fma8(acc, g0, w0);
        }
    }

    float* o = out + ((size_t)bt * NV + v) * NF + f0;
    *(float4*)(o)     = make_float4(acc[0], acc[1], acc[2], acc[3]);
    *(float4*)(o + 4) = make_float4(acc[4], acc[5], acc[6], acc[7]);
}

extern "C" void kernel_launch(void* const* d_in, const int* in_sizes, int n_in,
                              void* d_out, int out_size) {
    const float* x    = (const float*)d_in[0];
    const float* vals = (const float*)d_in[1];
    const int*   rows = (const int*)  d_in[2];
    const int*   cols = (const int*)  d_in[3];
    float*       out  = (float*)d_out;

    (void)in_sizes; (void)n_in; (void)out_size;

    // Fused convert + row_ptr scatter (independent work, block-partitioned).
    prep_kernel<<<CONV_BLOCKS + SCAT_BLOCKS, 256>>>(x, rows);

    // SpMM: warp per (v, pair-group). grid = (NV/4, 4).
    dim3 grid(NV / WARPS_CTA, PG);
    spmm_h_kernel<<<grid, WARPS_CTA * 32>>>(vals, cols, out);
}